// round 1
// baseline (speedup 1.0000x reference)
#include <cuda_runtime.h>

#define N_NODES 1000000
#define N_EDGES 8000000
#define EMB 64
#define NEG 0.01f
#define EPS 1e-10f

// ---------------- scratch (device globals; no runtime allocation) ----------------
__device__ float g_h[(size_t)N_NODES * EMB];   // projected features, [N][64]
__device__ int   g_cnt[N_NODES];               // per-row edge counts
__device__ int   g_start[N_NODES];             // CSR row starts (exclusive scan)
__device__ int   g_cursor[N_NODES];            // scatter cursors
__device__ int   g_perm[N_EDGES];              // col index grouped by row
__device__ int   g_bsum[1024];                 // scan block sums

static __device__ __forceinline__ float lrelu(float x) {
    return fmaxf(x, NEG * x);
}

// ---------------- 0: zero counts ----------------
__global__ void zero_kernel() {
    int i = blockIdx.x * blockDim.x + threadIdx.x;
    if (i < N_NODES) g_cnt[i] = 0;
}

// ---------------- 1: projection  h = lrelu(ego @ Wcomb + b) ----------------
// Wcomb[k][c*32+j] = W[c][k][j]. Thread-per-row, f32x2 packed FMAs,
// W broadcast from shared via 16B loads (reg pairs feed b64 operands directly).
__global__ __launch_bounds__(256) void proj_kernel(const float* __restrict__ ego,
                                                   const float* __restrict__ W,
                                                   const float* __restrict__ b) {
    __shared__ __align__(16) float Wsh[EMB][EMB];
    __shared__ float bsh[EMB];
    int tid = threadIdx.x;
    for (int i = tid; i < 2 * 64 * 32; i += blockDim.x) {
        int c = i >> 11;
        int k = (i >> 5) & 63;
        int j = i & 31;
        Wsh[k][c * 32 + j] = W[i];
    }
    if (tid < EMB) bsh[tid] = b[tid];   // b is [2][1][32] contiguous == [64]
    __syncthreads();

    int row = blockIdx.x * blockDim.x + tid;
    if (row >= N_NODES) return;

    const float4* egorow = (const float4*)(ego + (size_t)row * EMB);

    unsigned long long acc2[32];
#pragma unroll
    for (int m = 0; m < 32; m++) {
        float lo = bsh[2 * m], hi = bsh[2 * m + 1];
        asm("mov.b64 %0, {%1, %2};" : "=l"(acc2[m]) : "f"(lo), "f"(hi));
    }

#pragma unroll 1
    for (int kc = 0; kc < 4; kc++) {
        float4 e4[4];
#pragma unroll
        for (int q = 0; q < 4; q++) e4[q] = egorow[kc * 4 + q];
#pragma unroll
        for (int kq = 0; kq < 16; kq++) {
            float ev = ((const float*)e4)[kq];
            unsigned long long ep;
            asm("mov.b64 %0, {%1, %1};" : "=l"(ep) : "f"(ev));
            int k = kc * 16 + kq;
            const ulonglong2* wrow = (const ulonglong2*)(&Wsh[k][0]);
#pragma unroll
            for (int q = 0; q < 16; q++) {
                ulonglong2 w = wrow[q];   // LDS.128 broadcast
                asm("fma.rn.f32x2 %0, %1, %2, %0;" : "+l"(acc2[2 * q])     : "l"(ep), "l"(w.x));
                asm("fma.rn.f32x2 %0, %1, %2, %0;" : "+l"(acc2[2 * q + 1]) : "l"(ep), "l"(w.y));
            }
        }
    }

    float* hrow = g_h + (size_t)row * EMB;
#pragma unroll
    for (int q = 0; q < 16; q++) {
        float a, bb, c, d;
        asm("mov.b64 {%0, %1}, %2;" : "=f"(a), "=f"(bb) : "l"(acc2[2 * q]));
        asm("mov.b64 {%0, %1}, %2;" : "=f"(c), "=f"(d)  : "l"(acc2[2 * q + 1]));
        ((float4*)hrow)[q] = make_float4(lrelu(a), lrelu(bb), lrelu(c), lrelu(d));
    }
}

// ---------------- 2: histogram of destination rows ----------------
__global__ void hist_kernel(const int* __restrict__ row) {
    int e = blockIdx.x * blockDim.x + threadIdx.x;
    if (e < N_EDGES) atomicAdd(&g_cnt[row[e]], 1);
}

// ---------------- 3-5: exclusive scan of counts ----------------
__global__ void scan1_kernel() {
    __shared__ int wsum[8];
    int tid = threadIdx.x;
    int lane = tid & 31, wid = tid >> 5;
    int base = blockIdx.x * 1024 + tid * 4;
    int v[4];
#pragma unroll
    for (int i = 0; i < 4; i++) v[i] = (base + i < N_NODES) ? g_cnt[base + i] : 0;
    int s = v[0] + v[1] + v[2] + v[3];
    int x = s;
#pragma unroll
    for (int o = 1; o < 32; o <<= 1) {
        int y = __shfl_up_sync(0xffffffffu, x, o);
        if (lane >= o) x += y;
    }
    if (lane == 31) wsum[wid] = x;
    __syncthreads();
    if (wid == 0) {
        int w = (lane < 8) ? wsum[lane] : 0;
#pragma unroll
        for (int o = 1; o < 8; o <<= 1) {
            int y = __shfl_up_sync(0xffffffffu, w, o);
            if (lane >= o) w += y;
        }
        if (lane < 8) wsum[lane] = w;
        if (lane == 7) g_bsum[blockIdx.x] = w;
    }
    __syncthreads();
    int excl = x - s + (wid > 0 ? wsum[wid - 1] : 0);
#pragma unroll
    for (int i = 0; i < 4; i++) {
        if (base + i < N_NODES) g_start[base + i] = excl;
        excl += v[i];
    }
}

__global__ void scan2_kernel(int nb) {
    __shared__ int wsum[32];
    int tid = threadIdx.x, lane = tid & 31, wid = tid >> 5;
    int s = (tid < nb) ? g_bsum[tid] : 0;
    int x = s;
#pragma unroll
    for (int o = 1; o < 32; o <<= 1) {
        int y = __shfl_up_sync(0xffffffffu, x, o);
        if (lane >= o) x += y;
    }
    if (lane == 31) wsum[wid] = x;
    __syncthreads();
    if (wid == 0) {
        int w = wsum[lane];
#pragma unroll
        for (int o = 1; o < 32; o <<= 1) {
            int y = __shfl_up_sync(0xffffffffu, w, o);
            if (lane >= o) w += y;
        }
        wsum[lane] = w;
    }
    __syncthreads();
    int excl = x - s + (wid > 0 ? wsum[wid - 1] : 0);
    if (tid < nb) g_bsum[tid] = excl;
}

__global__ void scan3_kernel() {
    int i = blockIdx.x * blockDim.x + threadIdx.x;
    if (i < N_NODES) {
        int s = g_start[i] + g_bsum[i >> 10];
        g_start[i]  = s;
        g_cursor[i] = s;
    }
}

// ---------------- 6: scatter col indices grouped by row ----------------
__global__ void scatter_kernel(const int* __restrict__ row, const int* __restrict__ col) {
    int e = blockIdx.x * blockDim.x + threadIdx.x;
    if (e < N_EDGES) {
        int p = atomicAdd(&g_cursor[row[e]], 1);
        g_perm[p] = col[e];
    }
}

// ---------------- 7: fused edge softmax + aggregation ----------------
// 8 lanes per row (4 rows/warp). out[r] = (sum ex*h_col)/(sum ex + eps),
// ex = exp(lrelu(dot_c(h_row, h_col))) per channel.
__global__ __launch_bounds__(256) void agg_kernel(float* __restrict__ out) {
    int lane = threadIdx.x & 31;
    int warp_global = (blockIdx.x * blockDim.x + threadIdx.x) >> 5;
    int s = lane & 7;                      // position within 8-lane row group
    int row = warp_global * 4 + (lane >> 3);
    bool rowvalid = row < N_NODES;

    int start = 0, cnt = 0;
    float4 hr0 = make_float4(0.f, 0.f, 0.f, 0.f), hr1 = hr0;
    if (rowvalid) {
        start = g_start[row];
        cnt   = g_cnt[row];
        const float4* hp = (const float4*)(g_h + (size_t)row * EMB + s * 8);
        hr0 = hp[0];
        hr1 = hp[1];
    }

    int mx = cnt;
    mx = max(mx, __shfl_xor_sync(0xffffffffu, mx, 8));
    mx = max(mx, __shfl_xor_sync(0xffffffffu, mx, 16));

    float4 acc0 = make_float4(0.f, 0.f, 0.f, 0.f), acc1 = acc0;
    float accD = 0.f;

    for (int i = 0; i < mx; i++) {
        bool valid = i < cnt;
        float4 hc0 = make_float4(0.f, 0.f, 0.f, 0.f), hc1 = hc0;
        float p = 0.f;
        if (valid) {
            int c = g_perm[start + i];
            const float4* cp = (const float4*)(g_h + (size_t)c * EMB + s * 8);
            hc0 = cp[0];
            hc1 = cp[1];
            p = hr0.x * hc0.x + hr0.y * hc0.y + hr0.z * hc0.z + hr0.w * hc0.w
              + hr1.x * hc1.x + hr1.y * hc1.y + hr1.z * hc1.z + hr1.w * hc1.w;
        }
        // sum partial dot over the 4 lanes of each channel half
        p += __shfl_xor_sync(0xffffffffu, p, 1);
        p += __shfl_xor_sync(0xffffffffu, p, 2);
        if (valid) {
            float ex = __expf(lrelu(p));
            accD += ex;
            acc0.x += ex * hc0.x; acc0.y += ex * hc0.y;
            acc0.z += ex * hc0.z; acc0.w += ex * hc0.w;
            acc1.x += ex * hc1.x; acc1.y += ex * hc1.y;
            acc1.z += ex * hc1.z; acc1.w += ex * hc1.w;
        }
    }

    if (rowvalid) {
        float inv = 1.f / (accD + EPS);
        float4* op = (float4*)(out + (size_t)row * EMB + s * 8);
        op[0] = make_float4(acc0.x * inv, acc0.y * inv, acc0.z * inv, acc0.w * inv);
        op[1] = make_float4(acc1.x * inv, acc1.y * inv, acc1.z * inv, acc1.w * inv);
    }
}

// ---------------- launcher ----------------
extern "C" void kernel_launch(void* const* d_in, const int* in_sizes, int n_in,
                              void* d_out, int out_size) {
    const float* ego = (const float*)d_in[0];
    const float* W   = (const float*)d_in[1];
    const float* b   = (const float*)d_in[2];
    const int* rowi  = (const int*)d_in[3];
    const int* coli  = (const int*)d_in[4];
    float* out = (float*)d_out;

    const int NB_NODES = (N_NODES + 255) / 256;   // 3907
    const int NB_EDGES = (N_EDGES + 255) / 256;   // 31250
    const int NB_SCAN  = (N_NODES + 1023) / 1024; // 977

    zero_kernel<<<NB_NODES, 256>>>();
    proj_kernel<<<NB_NODES, 256>>>(ego, W, b);
    hist_kernel<<<NB_EDGES, 256>>>(rowi);
    scan1_kernel<<<NB_SCAN, 256>>>();
    scan2_kernel<<<1, 1024>>>(NB_SCAN);
    scan3_kernel<<<NB_NODES, 256>>>();
    scatter_kernel<<<NB_EDGES, 256>>>(rowi, coli);
    agg_kernel<<<(N_NODES / 32), 256>>>(out);
}

// round 2
// speedup vs baseline: 1.1405x; 1.1405x over previous
#include <cuda_runtime.h>
#include <cuda_fp16.h>

#define N_NODES 1000000
#define N_EDGES 8000000
#define EMB 64
#define NEG 0.01f
#define EPS 1e-10f

// ---------------- scratch (device globals; no runtime allocation) ----------------
__device__ __align__(128) __half g_h[(size_t)N_NODES * EMB]; // projected features fp16, [N][64] (128 MB, ~fits L2)
__device__ int   g_cnt[N_NODES];               // per-row edge counts
__device__ int   g_start[N_NODES];             // CSR row starts (exclusive scan)
__device__ int   g_cursor[N_NODES];            // scatter cursors
__device__ int   g_perm[N_EDGES];              // col index grouped by row
__device__ int   g_bsum[1024];                 // scan block sums

static __device__ __forceinline__ float lrelu(float x) {
    return fmaxf(x, NEG * x);
}

// ---------------- 0: zero counts ----------------
__global__ void zero_kernel() {
    int i = blockIdx.x * blockDim.x + threadIdx.x;
    if (i < N_NODES) g_cnt[i] = 0;
}

// ---------------- 1: projection  h = lrelu(ego @ Wcomb + b), fp16 output ----------------
__global__ __launch_bounds__(256) void proj_kernel(const float* __restrict__ ego,
                                                   const float* __restrict__ W,
                                                   const float* __restrict__ b) {
    __shared__ __align__(16) float Wsh[EMB][EMB];
    __shared__ float bsh[EMB];
    int tid = threadIdx.x;
    for (int i = tid; i < 2 * 64 * 32; i += blockDim.x) {
        int c = i >> 11;
        int k = (i >> 5) & 63;
        int j = i & 31;
        Wsh[k][c * 32 + j] = W[i];
    }
    if (tid < EMB) bsh[tid] = b[tid];   // b is [2][1][32] contiguous == [64]
    __syncthreads();

    int row = blockIdx.x * blockDim.x + tid;
    if (row >= N_NODES) return;

    const float4* egorow = (const float4*)(ego + (size_t)row * EMB);

    unsigned long long acc2[32];
#pragma unroll
    for (int m = 0; m < 32; m++) {
        float lo = bsh[2 * m], hi = bsh[2 * m + 1];
        asm("mov.b64 %0, {%1, %2};" : "=l"(acc2[m]) : "f"(lo), "f"(hi));
    }

#pragma unroll 1
    for (int kc = 0; kc < 4; kc++) {
        float4 e4[4];
#pragma unroll
        for (int q = 0; q < 4; q++) e4[q] = egorow[kc * 4 + q];
#pragma unroll
        for (int kq = 0; kq < 16; kq++) {
            float ev = ((const float*)e4)[kq];
            unsigned long long ep;
            asm("mov.b64 %0, {%1, %1};" : "=l"(ep) : "f"(ev));
            int k = kc * 16 + kq;
            const ulonglong2* wrow = (const ulonglong2*)(&Wsh[k][0]);
#pragma unroll
            for (int q = 0; q < 16; q++) {
                ulonglong2 w = wrow[q];   // LDS.128 broadcast
                asm("fma.rn.f32x2 %0, %1, %2, %0;" : "+l"(acc2[2 * q])     : "l"(ep), "l"(w.x));
                asm("fma.rn.f32x2 %0, %1, %2, %0;" : "+l"(acc2[2 * q + 1]) : "l"(ep), "l"(w.y));
            }
        }
    }

    // convert to fp16 and store 128B contiguous
    __half* hrow = g_h + (size_t)row * EMB;
    uint4* hv = (uint4*)hrow;
#pragma unroll
    for (int q = 0; q < 8; q++) {   // 8 halves per uint4
        uint4 pack;
        unsigned r[4];
#pragma unroll
        for (int t = 0; t < 4; t++) {
            float a, bb;
            asm("mov.b64 {%0, %1}, %2;" : "=f"(a), "=f"(bb) : "l"(acc2[4 * q + t]));
            __half2 h2 = __floats2half2_rn(lrelu(a), lrelu(bb));
            r[t] = *(unsigned*)&h2;
        }
        pack.x = r[0]; pack.y = r[1]; pack.z = r[2]; pack.w = r[3];
        hv[q] = pack;
    }
}

// ---------------- 2: histogram of destination rows ----------------
__global__ void hist_kernel(const int* __restrict__ row) {
    int e = blockIdx.x * blockDim.x + threadIdx.x;
    if (e < N_EDGES) atomicAdd(&g_cnt[row[e]], 1);
}

// ---------------- 3-5: exclusive scan of counts ----------------
__global__ void scan1_kernel() {
    __shared__ int wsum[8];
    int tid = threadIdx.x;
    int lane = tid & 31, wid = tid >> 5;
    int base = blockIdx.x * 1024 + tid * 4;
    int v[4];
#pragma unroll
    for (int i = 0; i < 4; i++) v[i] = (base + i < N_NODES) ? g_cnt[base + i] : 0;
    int s = v[0] + v[1] + v[2] + v[3];
    int x = s;
#pragma unroll
    for (int o = 1; o < 32; o <<= 1) {
        int y = __shfl_up_sync(0xffffffffu, x, o);
        if (lane >= o) x += y;
    }
    if (lane == 31) wsum[wid] = x;
    __syncthreads();
    if (wid == 0) {
        int w = (lane < 8) ? wsum[lane] : 0;
#pragma unroll
        for (int o = 1; o < 8; o <<= 1) {
            int y = __shfl_up_sync(0xffffffffu, w, o);
            if (lane >= o) w += y;
        }
        if (lane < 8) wsum[lane] = w;
        if (lane == 7) g_bsum[blockIdx.x] = w;
    }
    __syncthreads();
    int excl = x - s + (wid > 0 ? wsum[wid - 1] : 0);
#pragma unroll
    for (int i = 0; i < 4; i++) {
        if (base + i < N_NODES) g_start[base + i] = excl;
        excl += v[i];
    }
}

__global__ void scan2_kernel(int nb) {
    __shared__ int wsum[32];
    int tid = threadIdx.x, lane = tid & 31, wid = tid >> 5;
    int s = (tid < nb) ? g_bsum[tid] : 0;
    int x = s;
#pragma unroll
    for (int o = 1; o < 32; o <<= 1) {
        int y = __shfl_up_sync(0xffffffffu, x, o);
        if (lane >= o) x += y;
    }
    if (lane == 31) wsum[wid] = x;
    __syncthreads();
    if (wid == 0) {
        int w = wsum[lane];
#pragma unroll
        for (int o = 1; o < 32; o <<= 1) {
            int y = __shfl_up_sync(0xffffffffu, w, o);
            if (lane >= o) w += y;
        }
        wsum[lane] = w;
    }
    __syncthreads();
    int excl = x - s + (wid > 0 ? wsum[wid - 1] : 0);
    if (tid < nb) g_bsum[tid] = excl;
}

__global__ void scan3_kernel() {
    int i = blockIdx.x * blockDim.x + threadIdx.x;
    if (i < N_NODES) {
        int s = g_start[i] + g_bsum[i >> 10];
        g_start[i]  = s;
        g_cursor[i] = s;
    }
}

// ---------------- 6: scatter col indices grouped by row ----------------
__global__ void scatter_kernel(const int* __restrict__ row, const int* __restrict__ col) {
    int e = blockIdx.x * blockDim.x + threadIdx.x;
    if (e < N_EDGES) {
        int p = atomicAdd(&g_cursor[row[e]], 1);
        g_perm[p] = col[e];
    }
}

// ---------------- 7: fused edge softmax + aggregation (fp16 gathers) ----------------
// 8 lanes per row (4 rows/warp). Each edge gather is one 128B line (8 x 16B).
__global__ __launch_bounds__(256) void agg_kernel(float* __restrict__ out) {
    int lane = threadIdx.x & 31;
    int warp_global = (blockIdx.x * blockDim.x + threadIdx.x) >> 5;
    int s = lane & 7;                      // position within 8-lane row group
    int row = warp_global * 4 + (lane >> 3);
    bool rowvalid = row < N_NODES;

    int start = 0, cnt = 0;
    float hr[8];
#pragma unroll
    for (int q = 0; q < 8; q++) hr[q] = 0.f;
    if (rowvalid) {
        start = g_start[row];
        cnt   = g_cnt[row];
        uint4 v = *(const uint4*)(g_h + (size_t)row * EMB + s * 8);
        const __half2* p2 = (const __half2*)&v;
#pragma unroll
        for (int q = 0; q < 4; q++) {
            float2 f = __half22float2(p2[q]);
            hr[2 * q] = f.x; hr[2 * q + 1] = f.y;
        }
    }

    int mx = cnt;
    mx = max(mx, __shfl_xor_sync(0xffffffffu, mx, 8));
    mx = max(mx, __shfl_xor_sync(0xffffffffu, mx, 16));

    float acc[8];
#pragma unroll
    for (int q = 0; q < 8; q++) acc[q] = 0.f;
    float accD = 0.f;

    for (int i = 0; i < mx; i++) {
        bool valid = i < cnt;
        float hc[8];
        float p = 0.f;
        if (valid) {
            int c = g_perm[start + i];
            uint4 v = *(const uint4*)(g_h + (size_t)c * EMB + s * 8);
            const __half2* p2 = (const __half2*)&v;
#pragma unroll
            for (int q = 0; q < 4; q++) {
                float2 f = __half22float2(p2[q]);
                hc[2 * q] = f.x; hc[2 * q + 1] = f.y;
            }
#pragma unroll
            for (int q = 0; q < 8; q++) p = fmaf(hr[q], hc[q], p);
        } else {
#pragma unroll
            for (int q = 0; q < 8; q++) hc[q] = 0.f;
        }
        // sum partial dot over the 4 lanes of each channel half
        p += __shfl_xor_sync(0xffffffffu, p, 1);
        p += __shfl_xor_sync(0xffffffffu, p, 2);
        if (valid) {
            float ex = __expf(lrelu(p));
            accD += ex;
#pragma unroll
            for (int q = 0; q < 8; q++) acc[q] = fmaf(ex, hc[q], acc[q]);
        }
    }

    if (rowvalid) {
        float inv = 1.f / (accD + EPS);
        float4* op = (float4*)(out + (size_t)row * EMB + s * 8);
        op[0] = make_float4(acc[0] * inv, acc[1] * inv, acc[2] * inv, acc[3] * inv);
        op[1] = make_float4(acc[4] * inv, acc[5] * inv, acc[6] * inv, acc[7] * inv);
    }
}

// ---------------- launcher ----------------
extern "C" void kernel_launch(void* const* d_in, const int* in_sizes, int n_in,
                              void* d_out, int out_size) {
    const float* ego = (const float*)d_in[0];
    const float* W   = (const float*)d_in[1];
    const float* b   = (const float*)d_in[2];
    const int* rowi  = (const int*)d_in[3];
    const int* coli  = (const int*)d_in[4];
    float* out = (float*)d_out;

    const int NB_NODES = (N_NODES + 255) / 256;   // 3907
    const int NB_EDGES = (N_EDGES + 255) / 256;   // 31250
    const int NB_SCAN  = (N_NODES + 1023) / 1024; // 977

    zero_kernel<<<NB_NODES, 256>>>();
    proj_kernel<<<NB_NODES, 256>>>(ego, W, b);
    hist_kernel<<<NB_EDGES, 256>>>(rowi);
    scan1_kernel<<<NB_SCAN, 256>>>();
    scan2_kernel<<<1, 1024>>>(NB_SCAN);
    scan3_kernel<<<NB_NODES, 256>>>();
    scatter_kernel<<<NB_EDGES, 256>>>(rowi, coli);
    agg_kernel<<<(N_NODES / 32), 256>>>(out);
}